// round 12
// baseline (speedup 1.0000x reference)
#include <cuda_runtime.h>
#include <cuda_fp16.h>
#include <cuda_bf16.h>
#include <cstdint>
#include <cstddef>

#define BB 4096
#define NN 8192
#define DD 256

// ---- gemm1 tiling (fp16, warp-specialized in-kernel A conversion) ----
#define MT      64
#define KSPLIT  4
#define KPER    (NN / KSPLIT)     // 2048
#define KC      64
#define NCHUNK  (KPER / KC)       // 32
#define A_BYTES (64 * 128)        // 64 m-rows x 64 fp16 = 8KB
#define B_BYTES (256 * 128)       // 256 n-rows x 64 fp16 = 32KB
#define STG     (A_BYTES + B_BYTES)
#define GEMM_SMEM (3 * STG)       // 122880

// ---- mlp smem ----
#define MLP_IN_PL (128 * 512)
#define MLP_W_PL  (64 * 512)
#define MLP_SMEM  (2 * MLP_IN_PL + MLP_W_PL)  // 163840

// ---- prep dispatch (no convA anymore) ----
#define PREP_SORT   0
#define PREP_CONVE  1                              // 512 blocks (64x64 transpose tiles)
#define PREP_CONVW  (PREP_CONVE + (NN / 64) * (DD / 64))
#define PREP_GRID   (PREP_CONVW + (3 * DD * DD) / 1024)

// -------------------- device scratch --------------------
__device__ __align__(256) int   g_labels_s[BB];
__device__ __align__(256) int   g_idx_s[BB];
__device__ int   g_total;
__device__ __align__(256) float g_rsumP[KSPLIT * BB];      // per-ksplit rowsum partials (sorted pos)
__device__ __align__(256) __half g_EhT[(size_t)DD * NN];   // E transposed [n][k], fp16
__device__ __align__(256) __half g_Wh[3 * DD * DD];        // W fp16
__device__ __align__(256) __half g_hHi[BB * DD];
__device__ __align__(256) __half g_hLo[BB * DD];
__device__ __align__(256) __half g_h2Hi[BB * DD];
__device__ __align__(256) __half g_h2Lo[BB * DD];
__device__ __align__(256) float g_part[(size_t)KSPLIT * BB * DD];

// -------------------- helpers --------------------
__device__ __forceinline__ uint32_t smem_u32(const void* p) {
    uint32_t a;
    asm("{ .reg .u64 t; cvta.to.shared.u64 t, %1; cvt.u32.u64 %0, t; }" : "=r"(a) : "l"(p));
    return a;
}
#define CP16(dst, src) \
    asm volatile("cp.async.cg.shared.global [%0], [%1], 16;" \
        :: "r"(dst), "l"(__cvta_generic_to_global(src)) : "memory")
#define CP_COMMIT() asm volatile("cp.async.commit_group;" ::: "memory")

#define LDSM_X4(r0, r1, r2, r3, addr) \
    asm volatile("ldmatrix.sync.aligned.m8n8.x4.shared.b16 {%0,%1,%2,%3}, [%4];" \
        : "=r"(r0), "=r"(r1), "=r"(r2), "=r"(r3) : "r"(addr))

#define MMA_F16(d, a0, a1, a2, a3, b0, b1) \
    asm volatile("mma.sync.aligned.m16n8k16.row.col.f32.f16.f16.f32 " \
        "{%0,%1,%2,%3}, {%4,%5,%6,%7}, {%8,%9}, {%0,%1,%2,%3};" \
        : "+f"((d)[0]), "+f"((d)[1]), "+f"((d)[2]), "+f"((d)[3]) \
        : "r"(a0), "r"(a1), "r"(a2), "r"(a3), "r"(b0), "r"(b1))

#define STS128(addr, u0, u1, u2, u3) \
    asm volatile("st.shared.v4.b32 [%0], {%1,%2,%3,%4};" \
        :: "r"(addr), "r"(u0), "r"(u1), "r"(u2), "r"(u3) : "memory")

// ==================== 1) prep: sort + convE^T + convW ====================
__global__ void __launch_bounds__(256) prep_kernel(
    const int* __restrict__ labels, const int* __restrict__ nidx,
    const float* __restrict__ E,    const float* __restrict__ W,
    float* __restrict__ out_labels) {
    const int bid = blockIdx.x;
    const int t   = threadIdx.x;

    if (bid == PREP_SORT) {
        __shared__ int sc[256];
        int g0 = t * 16;
        int lab[16], nd[16];
        int c = 0;
#pragma unroll
        for (int j = 0; j < 16; j++) {
            lab[j] = labels[g0 + j];
            nd[j]  = nidx[g0 + j];
            c += (lab[j] != 0);
        }
        sc[t] = c;
        __syncthreads();
        for (int off = 1; off < 256; off <<= 1) {
            int v = sc[t];
            int add = (t >= off) ? sc[t - off] : 0;
            __syncthreads();
            sc[t] = v + add;
            __syncthreads();
        }
        int total = sc[255];
        int p     = sc[t] - c;
        if (t == 0) g_total = total;
#pragma unroll
        for (int j = 0; j < 16; j++) {
            int g = g0 + j;
            int dst;
            if (lab[j]) { dst = p; p++; }
            else        { dst = total + (g - p); }
            g_labels_s[dst] = lab[j];
            g_idx_s[dst]    = nd[j];
            if (out_labels) out_labels[dst] = (float)lab[j];
        }
    } else if (bid < PREP_CONVW) {
        // ---- convE^T: E[k][n] -> g_EhT[n][k] fp16, 64x64 tile ----
        __shared__ float tile[64][65];
        const int b2 = bid - PREP_CONVE;
        const int k0 = (b2 >> 2) * 64;
        const int n0 = (b2 & 3) * 64;
#pragma unroll
        for (int i = 0; i < 16; i++) {
            int idx = t + 256 * i;
            int kl = idx >> 6, nl = idx & 63;
            tile[kl][nl] = E[(size_t)(k0 + kl) * DD + n0 + nl];
        }
        __syncthreads();
        const int nl = t >> 2;
        const int ks = (t & 3) * 16;
        __half h[16];
#pragma unroll
        for (int j = 0; j < 16; j++)
            h[j] = __float2half_rn(tile[ks + j][nl]);
        uint4* dst = reinterpret_cast<uint4*>(g_EhT + (size_t)(n0 + nl) * NN + k0 + ks);
        dst[0] = *reinterpret_cast<uint4*>(h);
        dst[1] = *reinterpret_cast<uint4*>(h + 8);
    } else {
        // ---- convW: W -> fp16 ----
        size_t i = (size_t)(bid - PREP_CONVW) * 1024 + t * 4;
        float4 v = *reinterpret_cast<const float4*>(W + i);
        __half2* dst = reinterpret_cast<__half2*>(g_Wh + i);
        dst[0] = __float22half2_rn(make_float2(v.x, v.y));
        dst[1] = __float22half2_rn(make_float2(v.z, v.w));
    }
}

// ==================== 2) warp-specialized fp16 GEMM: A converted by producer warps ====================
// 512 threads: warps 0-7 MMA consumers, warps 8-15 producers (A fp32->fp16 + B cp.async).
// grid (KSPLIT, BB/MT): kb fast axis -> active tiles pack wave 1.
__global__ void __launch_bounds__(512, 1) gemm1_kernel(const float* __restrict__ A) {
    const int kb = blockIdx.x;
    const int m0 = blockIdx.y * MT;
    if (m0 >= g_total) return;

    extern __shared__ __align__(1024) char smem[];
    const uint32_t sb = smem_u32(smem);
    const int t = threadIdx.x, lane = t & 31, wid = t >> 5;
    const size_t kBase = (size_t)kb * KPER;
    const bool consumer = (wid < 8);

    if (consumer) {
        // ---------------- consumers: warps 0-7 ----------------
        const int wm = wid & 3, wn = wid >> 2;      // wn 0..1 (128-col bands)
        float acc[16][4];
#pragma unroll
        for (int f = 0; f < 16; f++)
#pragma unroll
            for (int q = 0; q < 4; q++) acc[f][q] = 0.f;

        const int q = lane >> 3, l7 = lane & 7;
        const int bnr   = wn * 128 + ((lane >> 4) << 3) + l7;
        const int bkoff = ((lane >> 3) & 1) * 16;

        __syncthreads();                             // stages 0,1 ready
        for (int c = 0; c < NCHUNK; c++) {
            const uint32_t Ab = sb + (uint32_t)((c % 3) * STG);
            const uint32_t Bb = Ab + A_BYTES;
#pragma unroll
            for (int ks = 0; ks < 4; ks++) {
                const int am  = wm * 16 + (q & 1) * 8 + l7;
                const int akB = ks * 32 + (q >> 1) * 16;
                uint32_t a0, a1, a2, a3;
                LDSM_X4(a0, a1, a2, a3, Ab + am * 128 + (uint32_t)(akB ^ ((am & 7) << 4)));
                const int kbB = ks * 32 + bkoff;
#pragma unroll
                for (int jb = 0; jb < 8; jb++) {
                    const int nrow = bnr + jb * 16;
                    uint32_t b0, b1, b2, b3;
                    LDSM_X4(b0, b1, b2, b3,
                            Bb + nrow * 128 + (uint32_t)(kbB ^ ((nrow & 7) << 4)));
                    MMA_F16(acc[jb * 2],     a0, a1, a2, a3, b0, b1);
                    MMA_F16(acc[jb * 2 + 1], a0, a1, a2, a3, b2, b3);
                }
            }
            __syncthreads();                         // stage c consumed / c+2 published
        }

        float* pbase = g_part + ((size_t)kb * BB + m0) * DD;
        const int row = wm * 16 + (lane >> 2);
        const int cb  = wn * 128 + (lane & 3) * 2;
#pragma unroll
        for (int f = 0; f < 16; f++) {
            const int n = cb + f * 8;
            *reinterpret_cast<float2*>(pbase + (size_t)row * DD + n) =
                make_float2(acc[f][0], acc[f][1]);
            *reinterpret_cast<float2*>(pbase + (size_t)(row + 8) * DD + n) =
                make_float2(acc[f][2], acc[f][3]);
        }
    } else {
        // ---------------- producers: warps 8-15 ----------------
        const int pt = t - 256;                      // 0..255
        const int r  = pt >> 2;                      // A row 0..63
        const int g0 = (pt & 3) * 2;                 // first of 2 granules (8 floats each)
        const int node = g_idx_s[m0 + r];
        const float* rowA = A + (size_t)node * NN + kBase;
        const uint32_t swr = (uint32_t)((r & 7) << 4);
        float rsum = 0.f;

        auto fill = [&](int c) {
            const uint32_t base = sb + (uint32_t)((c % 3) * STG);
            const size_t kOff = (size_t)c * KC;
            // A: 2 granules of 8 fp32 -> 8 fp16 (16B) each
#pragma unroll
            for (int j = 0; j < 2; j++) {
                const int g = g0 + j;
                const float* src = rowA + kOff + g * 8;
                float4 v0 = __ldg(reinterpret_cast<const float4*>(src));
                float4 v1 = __ldg(reinterpret_cast<const float4*>(src + 4));
                __half2 h0 = __float22half2_rn(make_float2(v0.x, v0.y));
                __half2 h1 = __float22half2_rn(make_float2(v0.z, v0.w));
                __half2 h2 = __float22half2_rn(make_float2(v1.x, v1.y));
                __half2 h3 = __float22half2_rn(make_float2(v1.z, v1.w));
                float2 f0 = __half22float2(h0), f1 = __half22float2(h1);
                float2 f2 = __half22float2(h2), f3 = __half22float2(h3);
                rsum += (f0.x + f0.y) + (f1.x + f1.y) + (f2.x + f2.y) + (f3.x + f3.y);
                uint32_t dst = base + r * 128 + ((uint32_t)(g * 16) ^ swr);
                STS128(dst,
                       *reinterpret_cast<uint32_t*>(&h0), *reinterpret_cast<uint32_t*>(&h1),
                       *reinterpret_cast<uint32_t*>(&h2), *reinterpret_cast<uint32_t*>(&h3));
            }
            // B: 8 x 16B cp.async
            const size_t kAbs = kBase + kOff;
#pragma unroll
            for (int i = 0; i < 8; i++) {
                int gg = pt + 256 * i;
                int n = gg >> 3, sB = gg & 7;
                uint32_t dst = base + A_BYTES + n * 128 +
                               (uint32_t)((sB * 16) ^ ((n & 7) << 4));
                CP16(dst, g_EhT + (size_t)n * NN + kAbs + sB * 8);
            }
            CP_COMMIT();
        };

        fill(0);
        fill(1);
        asm volatile("cp.async.wait_group 0;" ::: "memory");
        __syncthreads();                             // stages 0,1 ready
        for (int c = 0; c < NCHUNK; c++) {
            if (c + 2 < NCHUNK) {
                fill(c + 2);
                asm volatile("cp.async.wait_group 0;" ::: "memory");
            }
            __syncthreads();                         // publish c+2, consumers done with c
        }

        // per-ksplit rowsum partial (4 producer threads per row -> adjacent lanes)
        rsum += __shfl_xor_sync(0xffffffffu, rsum, 1);
        rsum += __shfl_xor_sync(0xffffffffu, rsum, 2);
        if ((pt & 3) == 0) g_rsumP[kb * BB + m0 + r] = rsum;
    }
}

// ==================== 3) finalize: reduce ksplits, normalize, gather, fp16-split ====================
__global__ void finalize_kernel(const float* __restrict__ E) {
    const int b = blockIdx.x;
    const int t = threadIdx.x;
    const int lab  = g_labels_s[b];
    const int node = g_idx_s[b];
    float v[4];
    if (lab) {
        float rs = g_rsumP[b] + g_rsumP[BB + b] + g_rsumP[2 * BB + b] + g_rsumP[3 * BB + b];
        float inv = 1.0f / rs;
        v[0] = v[1] = v[2] = v[3] = 0.f;
#pragma unroll
        for (int kb = 0; kb < KSPLIT; kb++) {
            float4 p = *reinterpret_cast<const float4*>(
                g_part + ((size_t)kb * BB + b) * DD + t * 4);
            v[0] += p.x; v[1] += p.y; v[2] += p.z; v[3] += p.w;
        }
#pragma unroll
        for (int j = 0; j < 4; j++) v[j] *= inv;
    } else {
        float4 p = *reinterpret_cast<const float4*>(E + (size_t)node * DD + t * 4);
        v[0] = p.x; v[1] = p.y; v[2] = p.z; v[3] = p.w;
    }
    size_t o = (size_t)b * DD + t * 4;
    __half hi[4], lo[4];
#pragma unroll
    for (int j = 0; j < 4; j++) {
        hi[j] = __float2half_rn(v[j]);
        lo[j] = __float2half_rn(v[j] - __half2float(hi[j]));
    }
    *reinterpret_cast<__half2*>(g_hHi + o)     = __halves2half2(hi[0], hi[1]);
    *reinterpret_cast<__half2*>(g_hHi + o + 2) = __halves2half2(hi[2], hi[3]);
    *reinterpret_cast<__half2*>(g_hLo + o)     = __halves2half2(lo[0], lo[1]);
    *reinterpret_cast<__half2*>(g_hLo + o + 2) = __halves2half2(lo[2], lo[3]);
}

// ==================== 4) MLP layer: fp16 x-split (2 MMAs) + bias + relu ====================
__global__ void __launch_bounds__(512, 1) mlp_kernel(
    const __half* __restrict__ inHi, const __half* __restrict__ inLo,
    const __half* __restrict__ Wh,   const float* __restrict__ bias,
    __half* __restrict__ outHi, __half* __restrict__ outLo,
    float* __restrict__ outF) {
    const int i0 = blockIdx.x * 128;
    const int o0 = blockIdx.y * 64;
    extern __shared__ __align__(1024) char smem[];
    const uint32_t sb = smem_u32(smem);
    const int t = threadIdx.x, lane = t & 31, wid = t >> 5;
    const int wm = wid & 7, wn = wid >> 3;
    const uint32_t sINhi = sb;
    const uint32_t sINlo = sb + MLP_IN_PL;
    const uint32_t sW    = sb + 2 * MLP_IN_PL;

    auto load_half = [&](int h) {
#pragma unroll
        for (int i = 0; i < 4; i++) {
            int g = t + 512 * i;
            int m = g >> 4, s = (g & 15) + h * 16;
            uint32_t off = m * 512 + (uint32_t)((s * 16) ^ ((m & 7) << 4));
            CP16(sINhi + off, inHi + (size_t)(i0 + m) * DD + s * 8);
            CP16(sINlo + off, inLo + (size_t)(i0 + m) * DD + s * 8);
        }
#pragma unroll
        for (int i = 0; i < 2; i++) {
            int gg = t + 512 * i;
            int n = gg >> 4, s = (gg & 15) + h * 16;
            uint32_t off = n * 512 + (uint32_t)((s * 16) ^ ((n & 7) << 4));
            CP16(sW + off, Wh + (size_t)(o0 + n) * DD + s * 8);
        }
    };

    float acc[4][4];
#pragma unroll
    for (int f = 0; f < 4; f++)
#pragma unroll
        for (int q = 0; q < 4; q++) acc[f][q] = 0.f;

    auto comp_half = [&](int h) {
        const int q = lane >> 3, l7 = lane & 7;
#pragma unroll
        for (int ksl = 0; ksl < 8; ksl++) {
            const int ks = h * 8 + ksl;
            uint32_t ah[4], al[4];
            {
                const int m  = wm * 16 + (q & 1) * 8 + l7;
                const int kB = ks * 32 + (q >> 1) * 16;
                const uint32_t off = m * 512 + (uint32_t)(kB ^ ((m & 7) << 4));
                LDSM_X4(ah[0], ah[1], ah[2], ah[3], sINhi + off);
                LDSM_X4(al[0], al[1], al[2], al[3], sINlo + off);
            }
            uint32_t bh[2][4];
#pragma unroll
            for (int nn = 0; nn < 2; nn++) {
                const int n  = wn * 32 + nn * 16 + (q >> 1) * 8 + l7;
                const int kB = ks * 32 + (q & 1) * 16;
                const uint32_t off = n * 512 + (uint32_t)(kB ^ ((n & 7) << 4));
                LDSM_X4(bh[nn][0], bh[nn][1], bh[nn][2], bh[nn][3], sW + off);
            }
#pragma unroll
            for (int nn = 0; nn < 2; nn++) {
                float* d0 = acc[nn * 2];
                float* d1 = acc[nn * 2 + 1];
                MMA_F16(d0, ah[0], ah[1], ah[2], ah[3], bh[nn][0], bh[nn][1]);
                MMA_F16(d0, al[0], al[1], al[2], al[3], bh[nn][0], bh[nn][1]);
                MMA_F16(d1, ah[0], ah[1], ah[2], ah[3], bh[nn][2], bh[nn][3]);
                MMA_F16(d1, al[0], al[1], al[2], al[3], bh[nn][2], bh[nn][3]);
            }
        }
    };

    load_half(0); CP_COMMIT();
    load_half(1); CP_COMMIT();
    asm volatile("cp.async.wait_group 1;" ::: "memory");
    __syncthreads();
    comp_half(0);
    asm volatile("cp.async.wait_group 0;" ::: "memory");
    __syncthreads();
    comp_half(1);

    const int row0 = i0 + wm * 16 + (lane >> 2);
#pragma unroll
    for (int f = 0; f < 4; f++) {
        const int col = o0 + wn * 32 + f * 8 + (lane & 3) * 2;
        const float b0 = bias[col], b1 = bias[col + 1];
        float y00 = fmaxf(acc[f][0] + b0, 0.f);
        float y01 = fmaxf(acc[f][1] + b1, 0.f);
        float y10 = fmaxf(acc[f][2] + b0, 0.f);
        float y11 = fmaxf(acc[f][3] + b1, 0.f);
        if (outF) {
            *reinterpret_cast<float2*>(outF + (size_t)row0 * DD + col) = make_float2(y00, y01);
            *reinterpret_cast<float2*>(outF + (size_t)(row0 + 8) * DD + col) = make_float2(y10, y11);
        } else {
            float y[4] = {y00, y01, y10, y11};
            __half hi[4], lo[4];
#pragma unroll
            for (int j = 0; j < 4; j++) {
                hi[j] = __float2half_rn(y[j]);
                lo[j] = __float2half_rn(y[j] - __half2float(hi[j]));
            }
            *reinterpret_cast<__half2*>(outHi + (size_t)row0 * DD + col) = __halves2half2(hi[0], hi[1]);
            *reinterpret_cast<__half2*>(outHi + (size_t)(row0 + 8) * DD + col) = __halves2half2(hi[2], hi[3]);
            *reinterpret_cast<__half2*>(outLo + (size_t)row0 * DD + col) = __halves2half2(lo[0], lo[1]);
            *reinterpret_cast<__half2*>(outLo + (size_t)(row0 + 8) * DD + col) = __halves2half2(lo[2], lo[3]);
        }
    }
}

// ==================== launch ====================
extern "C" void kernel_launch(void* const* d_in, const int* in_sizes, int n_in,
                              void* d_out, int out_size) {
    const int*   labels = (const int*)d_in[0];
    const int*   nidx   = (const int*)d_in[1];
    const float* A      = (const float*)d_in[2];
    const float* E      = (const float*)d_in[3];
    const float* W      = (const float*)d_in[4];
    const float* bias   = (const float*)d_in[5];

    float* out        = (float*)d_out;
    float* out_labels = nullptr;
    float* out_h      = out;
    if (out_size >= BB * DD + BB) {
        out_labels = out;
        out_h      = out + BB;
    }

    __half *hHi, *hLo, *h2Hi, *h2Lo, *Wh;
    cudaGetSymbolAddress((void**)&hHi,  g_hHi);
    cudaGetSymbolAddress((void**)&hLo,  g_hLo);
    cudaGetSymbolAddress((void**)&h2Hi, g_h2Hi);
    cudaGetSymbolAddress((void**)&h2Lo, g_h2Lo);
    cudaGetSymbolAddress((void**)&Wh,   g_Wh);

    cudaFuncSetAttribute(gemm1_kernel,
                         cudaFuncAttributeMaxDynamicSharedMemorySize, GEMM_SMEM);
    cudaFuncSetAttribute(mlp_kernel,
                         cudaFuncAttributeMaxDynamicSharedMemorySize, MLP_SMEM);

    prep_kernel<<<PREP_GRID, 256>>>(labels, nidx, E, W, out_labels);
    gemm1_kernel<<<dim3(KSPLIT, BB / MT), 512, GEMM_SMEM>>>(A);
    finalize_kernel<<<BB, 64>>>(E);
    mlp_kernel<<<dim3(BB / 128, DD / 64), 512, MLP_SMEM>>>(
        hHi, hLo, Wh, bias, h2Hi, h2Lo, nullptr);
    mlp_kernel<<<dim3(BB / 128, DD / 64), 512, MLP_SMEM>>>(
        h2Hi, h2Lo, Wh + DD * DD, bias + DD, hHi, hLo, nullptr);
    mlp_kernel<<<dim3(BB / 128, DD / 64), 512, MLP_SMEM>>>(
        hHi, hLo, Wh + 2 * DD * DD, bias + 2 * DD, nullptr, nullptr, out_h);
}

// round 16
// speedup vs baseline: 1.1379x; 1.1379x over previous
#include <cuda_runtime.h>
#include <cuda_fp16.h>
#include <cuda_bf16.h>
#include <cstdint>
#include <cstddef>

#define BB 4096
#define NN 8192
#define DD 256

// ---- gemm1 tiling (fp16, warp-specialized, fully-async A conversion) ----
#define MT      64
#define KSPLIT  4
#define KPER    (NN / KSPLIT)     // 2048
#define KC      64
#define NCHUNK  (KPER / KC)       // 32
#define OFF_A16 0                 // 64 rows x 128B fp16
#define OFF_B   8192              // 256 rows x 128B fp16
#define OFF_A32 40960             // 64 rows x 256B fp32 staging (linear)
#define STG     57344
#define GEMM_SMEM (3 * STG)       // 172032

// ---- mlp smem ----
#define MLP_IN_PL (128 * 512)
#define MLP_W_PL  (64 * 512)
#define MLP_SMEM  (2 * MLP_IN_PL + MLP_W_PL)  // 163840

// ---- prep dispatch ----
#define PREP_SORT   0
#define PREP_CONVE  1
#define PREP_CONVW  (PREP_CONVE + (NN / 64) * (DD / 64))
#define PREP_GRID   (PREP_CONVW + (3 * DD * DD) / 1024)

// -------------------- device scratch --------------------
__device__ __align__(256) int   g_labels_s[BB];
__device__ __align__(256) int   g_idx_s[BB];
__device__ int   g_total;
__device__ __align__(256) float g_rsumP[KSPLIT * BB];
__device__ __align__(256) __half g_EhT[(size_t)DD * NN];
__device__ __align__(256) __half g_Wh[3 * DD * DD];
__device__ __align__(256) __half g_hHi[BB * DD];
__device__ __align__(256) __half g_hLo[BB * DD];
__device__ __align__(256) __half g_h2Hi[BB * DD];
__device__ __align__(256) __half g_h2Lo[BB * DD];
__device__ __align__(256) float g_part[(size_t)KSPLIT * BB * DD];

// -------------------- helpers --------------------
__device__ __forceinline__ uint32_t smem_u32(const void* p) {
    uint32_t a;
    asm("{ .reg .u64 t; cvta.to.shared.u64 t, %1; cvt.u32.u64 %0, t; }" : "=r"(a) : "l"(p));
    return a;
}
#define CP16(dst, src) \
    asm volatile("cp.async.cg.shared.global [%0], [%1], 16;" \
        :: "r"(dst), "l"(__cvta_generic_to_global(src)) : "memory")
#define CP_COMMIT() asm volatile("cp.async.commit_group;" ::: "memory")

#define LDSM_X4(r0, r1, r2, r3, addr) \
    asm volatile("ldmatrix.sync.aligned.m8n8.x4.shared.b16 {%0,%1,%2,%3}, [%4];" \
        : "=r"(r0), "=r"(r1), "=r"(r2), "=r"(r3) : "r"(addr))

#define MMA_F16(d, a0, a1, a2, a3, b0, b1) \
    asm volatile("mma.sync.aligned.m16n8k16.row.col.f32.f16.f16.f32 " \
        "{%0,%1,%2,%3}, {%4,%5,%6,%7}, {%8,%9}, {%0,%1,%2,%3};" \
        : "+f"((d)[0]), "+f"((d)[1]), "+f"((d)[2]), "+f"((d)[3]) \
        : "r"(a0), "r"(a1), "r"(a2), "r"(a3), "r"(b0), "r"(b1))

#define LDS128F(x, y, z, w, addr) \
    asm volatile("ld.shared.v4.f32 {%0,%1,%2,%3}, [%4];" \
        : "=f"(x), "=f"(y), "=f"(z), "=f"(w) : "r"(addr))

#define STS64U(addr, u0, u1) \
    asm volatile("st.shared.v2.b32 [%0], {%1,%2};" :: "r"(addr), "r"(u0), "r"(u1) : "memory")

// ==================== 1) prep: sort + convE^T + convW ====================
__global__ void __launch_bounds__(256) prep_kernel(
    const int* __restrict__ labels, const int* __restrict__ nidx,
    const float* __restrict__ E,    const float* __restrict__ W,
    float* __restrict__ out_labels) {
    const int bid = blockIdx.x;
    const int t   = threadIdx.x;

    if (bid == PREP_SORT) {
        __shared__ int sc[256];
        int g0 = t * 16;
        int lab[16], nd[16];
        int c = 0;
#pragma unroll
        for (int j = 0; j < 16; j++) {
            lab[j] = labels[g0 + j];
            nd[j]  = nidx[g0 + j];
            c += (lab[j] != 0);
        }
        sc[t] = c;
        __syncthreads();
        for (int off = 1; off < 256; off <<= 1) {
            int v = sc[t];
            int add = (t >= off) ? sc[t - off] : 0;
            __syncthreads();
            sc[t] = v + add;
            __syncthreads();
        }
        int total = sc[255];
        int p     = sc[t] - c;
        if (t == 0) g_total = total;
#pragma unroll
        for (int j = 0; j < 16; j++) {
            int g = g0 + j;
            int dst;
            if (lab[j]) { dst = p; p++; }
            else        { dst = total + (g - p); }
            g_labels_s[dst] = lab[j];
            g_idx_s[dst]    = nd[j];
            if (out_labels) out_labels[dst] = (float)lab[j];
        }
    } else if (bid < PREP_CONVW) {
        __shared__ float tile[64][65];
        const int b2 = bid - PREP_CONVE;
        const int k0 = (b2 >> 2) * 64;
        const int n0 = (b2 & 3) * 64;
#pragma unroll
        for (int i = 0; i < 16; i++) {
            int idx = t + 256 * i;
            int kl = idx >> 6, nl = idx & 63;
            tile[kl][nl] = E[(size_t)(k0 + kl) * DD + n0 + nl];
        }
        __syncthreads();
        const int nl = t >> 2;
        const int ks = (t & 3) * 16;
        __half h[16];
#pragma unroll
        for (int j = 0; j < 16; j++)
            h[j] = __float2half_rn(tile[ks + j][nl]);
        uint4* dst = reinterpret_cast<uint4*>(g_EhT + (size_t)(n0 + nl) * NN + k0 + ks);
        dst[0] = *reinterpret_cast<uint4*>(h);
        dst[1] = *reinterpret_cast<uint4*>(h + 8);
    } else {
        size_t i = (size_t)(bid - PREP_CONVW) * 1024 + t * 4;
        float4 v = *reinterpret_cast<const float4*>(W + i);
        __half2* dst = reinterpret_cast<__half2*>(g_Wh + i);
        dst[0] = __float22half2_rn(make_float2(v.x, v.y));
        dst[1] = __float22half2_rn(make_float2(v.z, v.w));
    }
}

// ==================== 2) warp-specialized fp16 GEMM, fully-async A ====================
// 512 threads: warps 0-7 consumers, warps 8-15 producers (A fp32 cp.async -> smem cvt + B cp.async).
__global__ void __launch_bounds__(512, 1) gemm1_kernel(const float* __restrict__ A) {
    const int kb = blockIdx.x;
    const int m0 = blockIdx.y * MT;
    if (m0 >= g_total) return;

    extern __shared__ __align__(1024) char smem[];
    const uint32_t sb = smem_u32(smem);
    const int t = threadIdx.x, lane = t & 31, wid = t >> 5;
    const size_t kBase = (size_t)kb * KPER;

    if (wid < 8) {
        // ---------------- consumers ----------------
        const int wm = wid & 3, wn = wid >> 2;
        float acc[16][4];
#pragma unroll
        for (int f = 0; f < 16; f++)
#pragma unroll
            for (int q = 0; q < 4; q++) acc[f][q] = 0.f;

        const int q = lane >> 3, l7 = lane & 7;
        const int bnr   = wn * 128 + ((lane >> 4) << 3) + l7;
        const int bkoff = ((lane >> 3) & 1) * 16;

        __syncthreads();                             // stage 0 ready
        for (int c = 0; c < NCHUNK; c++) {
            const uint32_t Ab = sb + (uint32_t)((c % 3) * STG) + OFF_A16;
            const uint32_t Bb = sb + (uint32_t)((c % 3) * STG) + OFF_B;
#pragma unroll
            for (int ks = 0; ks < 4; ks++) {
                const int am  = wm * 16 + (q & 1) * 8 + l7;
                const int akB = ks * 32 + (q >> 1) * 16;
                uint32_t a0, a1, a2, a3;
                LDSM_X4(a0, a1, a2, a3, Ab + am * 128 + (uint32_t)(akB ^ ((am & 7) << 4)));
                const int kbB = ks * 32 + bkoff;
#pragma unroll
                for (int jb = 0; jb < 8; jb++) {
                    const int nrow = bnr + jb * 16;
                    uint32_t b0, b1, b2, b3;
                    LDSM_X4(b0, b1, b2, b3,
                            Bb + nrow * 128 + (uint32_t)(kbB ^ ((nrow & 7) << 4)));
                    MMA_F16(acc[jb * 2],     a0, a1, a2, a3, b0, b1);
                    MMA_F16(acc[jb * 2 + 1], a0, a1, a2, a3, b2, b3);
                }
            }
            __syncthreads();
        }

        float* pbase = g_part + ((size_t)kb * BB + m0) * DD;
        const int row = wm * 16 + (lane >> 2);
        const int cb  = wn * 128 + (lane & 3) * 2;
#pragma unroll
        for (int f = 0; f < 16; f++) {
            const int n = cb + f * 8;
            *reinterpret_cast<float2*>(pbase + (size_t)row * DD + n) =
                make_float2(acc[f][0], acc[f][1]);
            *reinterpret_cast<float2*>(pbase + (size_t)(row + 8) * DD + n) =
                make_float2(acc[f][2], acc[f][3]);
        }
    } else {
        // ---------------- producers ----------------
        const int pt = t - 256;                      // 0..255
        // A32 fill: granules g = pt + 256*i, row = g>>4, seg = g&15 (linear dst)
        const float* aSrc[4];
#pragma unroll
        for (int i = 0; i < 4; i++) {
            int row = (pt >> 4) + 16 * i;
            aSrc[i] = A + (size_t)g_idx_s[m0 + row] * NN + kBase + (pt & 15) * 4;
        }
        // convert: thread pt handles elements j*1024 + pt*4 .. +3 (quarter-stride, conflict-free)
        const uint32_t swr    = (uint32_t)(((pt >> 4) & 7) << 4);
        const uint32_t a16off = (uint32_t)(((pt & 15) * 8) ^ swr);
        float s[4] = {0.f, 0.f, 0.f, 0.f};

        auto fill = [&](int c) {
            const uint32_t base = sb + (uint32_t)((c % 3) * STG);
            const size_t kOff = (size_t)c * KC;
#pragma unroll
            for (int i = 0; i < 4; i++) {
                uint32_t dst = base + OFF_A32 + (uint32_t)((pt + 256 * i) * 16);
                CP16(dst, aSrc[i] + kOff);
            }
            const size_t kAbs = kBase + kOff;
#pragma unroll
            for (int i = 0; i < 8; i++) {
                int gg = pt + 256 * i;
                int n = gg >> 3, sB = gg & 7;
                uint32_t dst = base + OFF_B + n * 128 +
                               (uint32_t)((sB * 16) ^ ((n & 7) << 4));
                CP16(dst, g_EhT + (size_t)n * NN + kAbs + sB * 8);
            }
            CP_COMMIT();
        };

        auto convert = [&](int c) {
            const uint32_t base = sb + (uint32_t)((c % 3) * STG);
            const uint32_t a32 = base + OFF_A32;
            const uint32_t a16 = base + OFF_A16;
#pragma unroll
            for (int j = 0; j < 4; j++) {
                float x, y, z, w;
                LDS128F(x, y, z, w, a32 + (uint32_t)(j * 4096 + pt * 16));
                __half2 h0 = __float22half2_rn(make_float2(x, y));
                __half2 h1 = __float22half2_rn(make_float2(z, w));
                float2 f0 = __half22float2(h0), f1 = __half22float2(h1);
                s[j] += (f0.x + f0.y) + (f1.x + f1.y);
                const int row = j * 16 + (pt >> 4);
                STS64U(a16 + (uint32_t)(row * 128) + a16off,
                       *reinterpret_cast<uint32_t*>(&h0),
                       *reinterpret_cast<uint32_t*>(&h1));
            }
        };

        fill(0);
        fill(1);
        asm volatile("cp.async.wait_group 1;" ::: "memory");  // stage 0 arrived
        convert(0);
        __syncthreads();                             // publish stage 0
        for (int c = 0; c < NCHUNK; c++) {
            if (c + 2 < NCHUNK) {
                fill(c + 2);
                asm volatile("cp.async.wait_group 1;" ::: "memory");  // stage c+1 arrived
            } else {
                asm volatile("cp.async.wait_group 0;" ::: "memory");
            }
            if (c + 1 < NCHUNK) convert(c + 1);
            __syncthreads();                         // publish stage c+1
        }

        // rowsum partials: reduce within 16-lane groups (rows j*16 + (pt>>4))
#pragma unroll
        for (int j = 0; j < 4; j++) {
            s[j] += __shfl_xor_sync(0xffffffffu, s[j], 1);
            s[j] += __shfl_xor_sync(0xffffffffu, s[j], 2);
            s[j] += __shfl_xor_sync(0xffffffffu, s[j], 4);
            s[j] += __shfl_xor_sync(0xffffffffu, s[j], 8);
        }
        if ((lane & 15) == 0) {
            const int rbase = pt >> 4;
#pragma unroll
            for (int j = 0; j < 4; j++)
                g_rsumP[kb * BB + m0 + j * 16 + rbase] = s[j];
        }
    }
}

// ==================== 3) finalize: reduce ksplits, normalize, gather, fp16-split ====================
__global__ void finalize_kernel(const float* __restrict__ E) {
    const int b = blockIdx.x;
    const int t = threadIdx.x;
    const int lab  = g_labels_s[b];
    const int node = g_idx_s[b];
    float v[4];
    if (lab) {
        float rs = g_rsumP[b] + g_rsumP[BB + b] + g_rsumP[2 * BB + b] + g_rsumP[3 * BB + b];
        float inv = 1.0f / rs;
        v[0] = v[1] = v[2] = v[3] = 0.f;
#pragma unroll
        for (int kb = 0; kb < KSPLIT; kb++) {
            float4 p = *reinterpret_cast<const float4*>(
                g_part + ((size_t)kb * BB + b) * DD + t * 4);
            v[0] += p.x; v[1] += p.y; v[2] += p.z; v[3] += p.w;
        }
#pragma unroll
        for (int j = 0; j < 4; j++) v[j] *= inv;
    } else {
        float4 p = *reinterpret_cast<const float4*>(E + (size_t)node * DD + t * 4);
        v[0] = p.x; v[1] = p.y; v[2] = p.z; v[3] = p.w;
    }
    size_t o = (size_t)b * DD + t * 4;
    __half hi[4], lo[4];
#pragma unroll
    for (int j = 0; j < 4; j++) {
        hi[j] = __float2half_rn(v[j]);
        lo[j] = __float2half_rn(v[j] - __half2float(hi[j]));
    }
    *reinterpret_cast<__half2*>(g_hHi + o)     = __halves2half2(hi[0], hi[1]);
    *reinterpret_cast<__half2*>(g_hHi + o + 2) = __halves2half2(hi[2], hi[3]);
    *reinterpret_cast<__half2*>(g_hLo + o)     = __halves2half2(lo[0], lo[1]);
    *reinterpret_cast<__half2*>(g_hLo + o + 2) = __halves2half2(lo[2], lo[3]);
}

// ==================== 4) MLP layer: fp16 x-split (2 MMAs) + bias + relu ====================
__global__ void __launch_bounds__(512, 1) mlp_kernel(
    const __half* __restrict__ inHi, const __half* __restrict__ inLo,
    const __half* __restrict__ Wh,   const float* __restrict__ bias,
    __half* __restrict__ outHi, __half* __restrict__ outLo,
    float* __restrict__ outF) {
    const int i0 = blockIdx.x * 128;
    const int o0 = blockIdx.y * 64;
    extern __shared__ __align__(1024) char smem[];
    const uint32_t sb = smem_u32(smem);
    const int t = threadIdx.x, lane = t & 31, wid = t >> 5;
    const int wm = wid & 7, wn = wid >> 3;
    const uint32_t sINhi = sb;
    const uint32_t sINlo = sb + MLP_IN_PL;
    const uint32_t sW    = sb + 2 * MLP_IN_PL;

    auto load_half = [&](int h) {
#pragma unroll
        for (int i = 0; i < 4; i++) {
            int g = t + 512 * i;
            int m = g >> 4, s = (g & 15) + h * 16;
            uint32_t off = m * 512 + (uint32_t)((s * 16) ^ ((m & 7) << 4));
            CP16(sINhi + off, inHi + (size_t)(i0 + m) * DD + s * 8);
            CP16(sINlo + off, inLo + (size_t)(i0 + m) * DD + s * 8);
        }
#pragma unroll
        for (int i = 0; i < 2; i++) {
            int gg = t + 512 * i;
            int n = gg >> 4, s = (gg & 15) + h * 16;
            uint32_t off = n * 512 + (uint32_t)((s * 16) ^ ((n & 7) << 4));
            CP16(sW + off, Wh + (size_t)(o0 + n) * DD + s * 8);
        }
    };

    float acc[4][4];
#pragma unroll
    for (int f = 0; f < 4; f++)
#pragma unroll
        for (int q = 0; q < 4; q++) acc[f][q] = 0.f;

    auto comp_half = [&](int h) {
        const int q = lane >> 3, l7 = lane & 7;
#pragma unroll
        for (int ksl = 0; ksl < 8; ksl++) {
            const int ks = h * 8 + ksl;
            uint32_t ah[4], al[4];
            {
                const int m  = wm * 16 + (q & 1) * 8 + l7;
                const int kB = ks * 32 + (q >> 1) * 16;
                const uint32_t off = m * 512 + (uint32_t)(kB ^ ((m & 7) << 4));
                LDSM_X4(ah[0], ah[1], ah[2], ah[3], sINhi + off);
                LDSM_X4(al[0], al[1], al[2], al[3], sINlo + off);
            }
            uint32_t bh[2][4];
#pragma unroll
            for (int nn = 0; nn < 2; nn++) {
                const int n  = wn * 32 + nn * 16 + (q >> 1) * 8 + l7;
                const int kB = ks * 32 + (q & 1) * 16;
                const uint32_t off = n * 512 + (uint32_t)(kB ^ ((n & 7) << 4));
                LDSM_X4(bh[nn][0], bh[nn][1], bh[nn][2], bh[nn][3], sW + off);
            }
#pragma unroll
            for (int nn = 0; nn < 2; nn++) {
                float* d0 = acc[nn * 2];
                float* d1 = acc[nn * 2 + 1];
                MMA_F16(d0, ah[0], ah[1], ah[2], ah[3], bh[nn][0], bh[nn][1]);
                MMA_F16(d0, al[0], al[1], al[2], al[3], bh[nn][0], bh[nn][1]);
                MMA_F16(d1, ah[0], ah[1], ah[2], ah[3], bh[nn][2], bh[nn][3]);
                MMA_F16(d1, al[0], al[1], al[2], al[3], bh[nn][2], bh[nn][3]);
            }
        }
    };

    load_half(0); CP_COMMIT();
    load_half(1); CP_COMMIT();
    asm volatile("cp.async.wait_group 1;" ::: "memory");
    __syncthreads();
    comp_half(0);
    asm volatile("cp.async.wait_group 0;" ::: "memory");
    __syncthreads();
    comp_half(1);

    const int row0 = i0 + wm * 16 + (lane >> 2);
#pragma unroll
    for (int f = 0; f < 4; f++) {
        const int col = o0 + wn * 32 + f * 8 + (lane & 3) * 2;
        const float b0 = bias[col], b1 = bias[col + 1];
        float y00 = fmaxf(acc[f][0] + b0, 0.f);
        float y01 = fmaxf(acc[f][1] + b1, 0.f);
        float y10 = fmaxf(acc[f][2] + b0, 0.f);
        float y11 = fmaxf(acc[f][3] + b1, 0.f);
        if (outF) {
            *reinterpret_cast<float2*>(outF + (size_t)row0 * DD + col) = make_float2(y00, y01);
            *reinterpret_cast<float2*>(outF + (size_t)(row0 + 8) * DD + col) = make_float2(y10, y11);
        } else {
            float y[4] = {y00, y01, y10, y11};
            __half hi[4], lo[4];
#pragma unroll
            for (int j = 0; j < 4; j++) {
                hi[j] = __float2half_rn(y[j]);
                lo[j] = __float2half_rn(y[j] - __half2float(hi[j]));
            }
            *reinterpret_cast<__half2*>(outHi + (size_t)row0 * DD + col) = __halves2half2(hi[0], hi[1]);
            *reinterpret_cast<__half2*>(outHi + (size_t)(row0 + 8) * DD + col) = __halves2half2(hi[2], hi[3]);
            *reinterpret_cast<__half2*>(outLo + (size_t)row0 * DD + col) = __halves2half2(lo[0], lo[1]);
            *reinterpret_cast<__half2*>(outLo + (size_t)(row0 + 8) * DD + col) = __halves2half2(lo[2], lo[3]);
        }
    }
}

// ==================== launch ====================
extern "C" void kernel_launch(void* const* d_in, const int* in_sizes, int n_in,
                              void* d_out, int out_size) {
    const int*   labels = (const int*)d_in[0];
    const int*   nidx   = (const int*)d_in[1];
    const float* A      = (const float*)d_in[2];
    const float* E      = (const float*)d_in[3];
    const float* W      = (const float*)d_in[4];
    const float* bias   = (const float*)d_in[5];

    float* out        = (float*)d_out;
    float* out_labels = nullptr;
    float* out_h      = out;
    if (out_size >= BB * DD + BB) {
        out_labels = out;
        out_h      = out + BB;
    }

    __half *hHi, *hLo, *h2Hi, *h2Lo, *Wh;
    cudaGetSymbolAddress((void**)&hHi,  g_hHi);
    cudaGetSymbolAddress((void**)&hLo,  g_hLo);
    cudaGetSymbolAddress((void**)&h2Hi, g_h2Hi);
    cudaGetSymbolAddress((void**)&h2Lo, g_h2Lo);
    cudaGetSymbolAddress((void**)&Wh,   g_Wh);

    cudaFuncSetAttribute(gemm1_kernel,
                         cudaFuncAttributeMaxDynamicSharedMemorySize, GEMM_SMEM);
    cudaFuncSetAttribute(mlp_kernel,
                         cudaFuncAttributeMaxDynamicSharedMemorySize, MLP_SMEM);

    prep_kernel<<<PREP_GRID, 256>>>(labels, nidx, E, W, out_labels);
    gemm1_kernel<<<dim3(KSPLIT, BB / MT), 512, GEMM_SMEM>>>(A);
    finalize_kernel<<<BB, 64>>>(E);
    mlp_kernel<<<dim3(BB / 128, DD / 64), 512, MLP_SMEM>>>(
        hHi, hLo, Wh, bias, h2Hi, h2Lo, nullptr);
    mlp_kernel<<<dim3(BB / 128, DD / 64), 512, MLP_SMEM>>>(
        h2Hi, h2Lo, Wh + DD * DD, bias + DD, hHi, hLo, nullptr);
    mlp_kernel<<<dim3(BB / 128, DD / 64), 512, MLP_SMEM>>>(
        hHi, hLo, Wh + 2 * DD * DD, bias + 2 * DD, nullptr, nullptr, out_h);
}

// round 17
// speedup vs baseline: 1.1419x; 1.0035x over previous
#include <cuda_runtime.h>
#include <cuda_fp16.h>
#include <cuda_bf16.h>
#include <cstdint>
#include <cstddef>

#define BB 4096
#define NN 8192
#define DD 256

// ---- gemm1 tiling (fp16, warp-specialized, fully-async A conversion) ----
#define MT      64
#define KSPLIT  4
#define KPER    (NN / KSPLIT)     // 2048
#define KC      64
#define NCHUNK  (KPER / KC)       // 32
#define OFF_A16 0                 // 64 rows x 128B fp16
#define OFF_B   8192              // 256 rows x 128B fp16
#define OFF_A32 40960             // 64 rows x 256B fp32 staging (linear)
#define STG     57344
#define GEMM_SMEM (3 * STG)       // 172032

// ---- mlp smem ----
#define MLP_IN_PL (128 * 512)
#define MLP_W_PL  (64 * 512)
#define MLP_SMEM  (2 * MLP_IN_PL + MLP_W_PL)  // 163840

// ---- prep dispatch ----
#define PREP_SORT   0
#define PREP_CONVE  1
#define PREP_CONVW  (PREP_CONVE + (NN / 64) * (DD / 64))
#define PREP_GRID   (PREP_CONVW + (3 * DD * DD) / 1024)

// -------------------- device scratch --------------------
__device__ __align__(256) int   g_labels_s[BB];
__device__ __align__(256) int   g_idx_s[BB];
__device__ int   g_total;
__device__ __align__(256) float g_rsumP[KSPLIT * BB];
__device__ __align__(256) __half g_EhT[(size_t)DD * NN];
__device__ __align__(256) __half g_Wh[3 * DD * DD];
__device__ __align__(256) __half g_hHi[BB * DD];
__device__ __align__(256) __half g_hLo[BB * DD];
__device__ __align__(256) __half g_h2Hi[BB * DD];
__device__ __align__(256) __half g_h2Lo[BB * DD];
__device__ __align__(256) float g_part[(size_t)KSPLIT * BB * DD];

// -------------------- helpers --------------------
__device__ __forceinline__ uint32_t smem_u32(const void* p) {
    uint32_t a;
    asm("{ .reg .u64 t; cvta.to.shared.u64 t, %1; cvt.u32.u64 %0, t; }" : "=r"(a) : "l"(p));
    return a;
}
#define CP16(dst, src) \
    asm volatile("cp.async.cg.shared.global [%0], [%1], 16;" \
        :: "r"(dst), "l"(__cvta_generic_to_global(src)) : "memory")
#define CP_COMMIT() asm volatile("cp.async.commit_group;" ::: "memory")

#define LDSM_X4(r0, r1, r2, r3, addr) \
    asm volatile("ldmatrix.sync.aligned.m8n8.x4.shared.b16 {%0,%1,%2,%3}, [%4];" \
        : "=r"(r0), "=r"(r1), "=r"(r2), "=r"(r3) : "r"(addr))

#define MMA_F16(d, a0, a1, a2, a3, b0, b1) \
    asm volatile("mma.sync.aligned.m16n8k16.row.col.f32.f16.f16.f32 " \
        "{%0,%1,%2,%3}, {%4,%5,%6,%7}, {%8,%9}, {%0,%1,%2,%3};" \
        : "+f"((d)[0]), "+f"((d)[1]), "+f"((d)[2]), "+f"((d)[3]) \
        : "r"(a0), "r"(a1), "r"(a2), "r"(a3), "r"(b0), "r"(b1))

#define LDS128F(x, y, z, w, addr) \
    asm volatile("ld.shared.v4.f32 {%0,%1,%2,%3}, [%4];" \
        : "=f"(x), "=f"(y), "=f"(z), "=f"(w) : "r"(addr))

#define STS64U(addr, u0, u1) \
    asm volatile("st.shared.v2.b32 [%0], {%1,%2};" :: "r"(addr), "r"(u0), "r"(u1) : "memory")

// ==================== 1) prep: sort + convE^T + convW ====================
__global__ void __launch_bounds__(256) prep_kernel(
    const int* __restrict__ labels, const int* __restrict__ nidx,
    const float* __restrict__ E,    const float* __restrict__ W,
    float* __restrict__ out_labels) {
    const int bid = blockIdx.x;
    const int t   = threadIdx.x;

    if (bid == PREP_SORT) {
        __shared__ int sc[256];
        int g0 = t * 16;
        int lab[16], nd[16];
        int c = 0;
#pragma unroll
        for (int j = 0; j < 16; j++) {
            lab[j] = labels[g0 + j];
            nd[j]  = nidx[g0 + j];
            c += (lab[j] != 0);
        }
        sc[t] = c;
        __syncthreads();
        for (int off = 1; off < 256; off <<= 1) {
            int v = sc[t];
            int add = (t >= off) ? sc[t - off] : 0;
            __syncthreads();
            sc[t] = v + add;
            __syncthreads();
        }
        int total = sc[255];
        int p     = sc[t] - c;
        if (t == 0) g_total = total;
#pragma unroll
        for (int j = 0; j < 16; j++) {
            int g = g0 + j;
            int dst;
            if (lab[j]) { dst = p; p++; }
            else        { dst = total + (g - p); }
            g_labels_s[dst] = lab[j];
            g_idx_s[dst]    = nd[j];
            if (out_labels) out_labels[dst] = (float)lab[j];
        }
    } else if (bid < PREP_CONVW) {
        __shared__ float tile[64][65];
        const int b2 = bid - PREP_CONVE;
        const int k0 = (b2 >> 2) * 64;
        const int n0 = (b2 & 3) * 64;
#pragma unroll
        for (int i = 0; i < 16; i++) {
            int idx = t + 256 * i;
            int kl = idx >> 6, nl = idx & 63;
            tile[kl][nl] = E[(size_t)(k0 + kl) * DD + n0 + nl];
        }
        __syncthreads();
        const int nl = t >> 2;
        const int ks = (t & 3) * 16;
        __half h[16];
#pragma unroll
        for (int j = 0; j < 16; j++)
            h[j] = __float2half_rn(tile[ks + j][nl]);
        uint4* dst = reinterpret_cast<uint4*>(g_EhT + (size_t)(n0 + nl) * NN + k0 + ks);
        dst[0] = *reinterpret_cast<uint4*>(h);
        dst[1] = *reinterpret_cast<uint4*>(h + 8);
    } else {
        size_t i = (size_t)(bid - PREP_CONVW) * 1024 + t * 4;
        float4 v = *reinterpret_cast<const float4*>(W + i);
        __half2* dst = reinterpret_cast<__half2*>(g_Wh + i);
        dst[0] = __float22half2_rn(make_float2(v.x, v.y));
        dst[1] = __float22half2_rn(make_float2(v.z, v.w));
    }
}

// ==================== 2) warp-specialized fp16 GEMM, fully-async A ====================
// 512 threads: warps 0-7 consumers, warps 8-15 producers (A fp32 cp.async -> smem cvt + B cp.async).
__global__ void __launch_bounds__(512, 1) gemm1_kernel(const float* __restrict__ A) {
    const int kb = blockIdx.x;
    const int m0 = blockIdx.y * MT;
    if (m0 >= g_total) return;

    extern __shared__ __align__(1024) char smem[];
    const uint32_t sb = smem_u32(smem);
    const int t = threadIdx.x, lane = t & 31, wid = t >> 5;
    const size_t kBase = (size_t)kb * KPER;

    if (wid < 8) {
        // ---------------- consumers ----------------
        const int wm = wid & 3, wn = wid >> 2;
        float acc[16][4];
#pragma unroll
        for (int f = 0; f < 16; f++)
#pragma unroll
            for (int q = 0; q < 4; q++) acc[f][q] = 0.f;

        const int q = lane >> 3, l7 = lane & 7;
        const int bnr   = wn * 128 + ((lane >> 4) << 3) + l7;
        const int bkoff = ((lane >> 3) & 1) * 16;

        __syncthreads();                             // stage 0 ready
        for (int c = 0; c < NCHUNK; c++) {
            const uint32_t Ab = sb + (uint32_t)((c % 3) * STG) + OFF_A16;
            const uint32_t Bb = sb + (uint32_t)((c % 3) * STG) + OFF_B;
#pragma unroll
            for (int ks = 0; ks < 4; ks++) {
                const int am  = wm * 16 + (q & 1) * 8 + l7;
                const int akB = ks * 32 + (q >> 1) * 16;
                uint32_t a0, a1, a2, a3;
                LDSM_X4(a0, a1, a2, a3, Ab + am * 128 + (uint32_t)(akB ^ ((am & 7) << 4)));
                const int kbB = ks * 32 + bkoff;
#pragma unroll
                for (int jb = 0; jb < 8; jb++) {
                    const int nrow = bnr + jb * 16;
                    uint32_t b0, b1, b2, b3;
                    LDSM_X4(b0, b1, b2, b3,
                            Bb + nrow * 128 + (uint32_t)(kbB ^ ((nrow & 7) << 4)));
                    MMA_F16(acc[jb * 2],     a0, a1, a2, a3, b0, b1);
                    MMA_F16(acc[jb * 2 + 1], a0, a1, a2, a3, b2, b3);
                }
            }
            __syncthreads();
        }

        float* pbase = g_part + ((size_t)kb * BB + m0) * DD;
        const int row = wm * 16 + (lane >> 2);
        const int cb  = wn * 128 + (lane & 3) * 2;
#pragma unroll
        for (int f = 0; f < 16; f++) {
            const int n = cb + f * 8;
            *reinterpret_cast<float2*>(pbase + (size_t)row * DD + n) =
                make_float2(acc[f][0], acc[f][1]);
            *reinterpret_cast<float2*>(pbase + (size_t)(row + 8) * DD + n) =
                make_float2(acc[f][2], acc[f][3]);
        }
    } else {
        // ---------------- producers ----------------
        const int pt = t - 256;                      // 0..255
        // A32 fill: granules g = pt + 256*i, row = g>>4, seg = g&15 (linear dst)
        const float* aSrc[4];
#pragma unroll
        for (int i = 0; i < 4; i++) {
            int row = (pt >> 4) + 16 * i;
            aSrc[i] = A + (size_t)g_idx_s[m0 + row] * NN + kBase + (pt & 15) * 4;
        }
        // convert: thread pt handles elements j*1024 + pt*4 .. +3 (quarter-stride, conflict-free)
        const uint32_t swr    = (uint32_t)(((pt >> 4) & 7) << 4);
        const uint32_t a16off = (uint32_t)(((pt & 15) * 8) ^ swr);
        float s[4] = {0.f, 0.f, 0.f, 0.f};

        auto fill = [&](int c) {
            const uint32_t base = sb + (uint32_t)((c % 3) * STG);
            const size_t kOff = (size_t)c * KC;
#pragma unroll
            for (int i = 0; i < 4; i++) {
                uint32_t dst = base + OFF_A32 + (uint32_t)((pt + 256 * i) * 16);
                CP16(dst, aSrc[i] + kOff);
            }
            const size_t kAbs = kBase + kOff;
#pragma unroll
            for (int i = 0; i < 8; i++) {
                int gg = pt + 256 * i;
                int n = gg >> 3, sB = gg & 7;
                uint32_t dst = base + OFF_B + n * 128 +
                               (uint32_t)((sB * 16) ^ ((n & 7) << 4));
                CP16(dst, g_EhT + (size_t)n * NN + kAbs + sB * 8);
            }
            CP_COMMIT();
        };

        auto convert = [&](int c) {
            const uint32_t base = sb + (uint32_t)((c % 3) * STG);
            const uint32_t a32 = base + OFF_A32;
            const uint32_t a16 = base + OFF_A16;
#pragma unroll
            for (int j = 0; j < 4; j++) {
                float x, y, z, w;
                LDS128F(x, y, z, w, a32 + (uint32_t)(j * 4096 + pt * 16));
                __half2 h0 = __float22half2_rn(make_float2(x, y));
                __half2 h1 = __float22half2_rn(make_float2(z, w));
                float2 f0 = __half22float2(h0), f1 = __half22float2(h1);
                s[j] += (f0.x + f0.y) + (f1.x + f1.y);
                const int row = j * 16 + (pt >> 4);
                STS64U(a16 + (uint32_t)(row * 128) + a16off,
                       *reinterpret_cast<uint32_t*>(&h0),
                       *reinterpret_cast<uint32_t*>(&h1));
            }
        };

        fill(0);
        fill(1);
        asm volatile("cp.async.wait_group 1;" ::: "memory");  // stage 0 arrived
        convert(0);
        __syncthreads();                             // publish stage 0
        for (int c = 0; c < NCHUNK; c++) {
            if (c + 2 < NCHUNK) {
                fill(c + 2);
                asm volatile("cp.async.wait_group 1;" ::: "memory");  // stage c+1 arrived
            } else {
                asm volatile("cp.async.wait_group 0;" ::: "memory");
            }
            if (c + 1 < NCHUNK) convert(c + 1);
            __syncthreads();                         // publish stage c+1
        }

        // rowsum partials: reduce within 16-lane groups (rows j*16 + (pt>>4))
#pragma unroll
        for (int j = 0; j < 4; j++) {
            s[j] += __shfl_xor_sync(0xffffffffu, s[j], 1);
            s[j] += __shfl_xor_sync(0xffffffffu, s[j], 2);
            s[j] += __shfl_xor_sync(0xffffffffu, s[j], 4);
            s[j] += __shfl_xor_sync(0xffffffffu, s[j], 8);
        }
        if ((lane & 15) == 0) {
            const int rbase = pt >> 4;
#pragma unroll
            for (int j = 0; j < 4; j++)
                g_rsumP[kb * BB + m0 + j * 16 + rbase] = s[j];
        }
    }
}

// ==================== 3) finalize: reduce ksplits, normalize, gather, fp16-split ====================
__global__ void finalize_kernel(const float* __restrict__ E) {
    const int b = blockIdx.x;
    const int t = threadIdx.x;
    const int lab  = g_labels_s[b];
    const int node = g_idx_s[b];
    float v[4];
    if (lab) {
        float rs = g_rsumP[b] + g_rsumP[BB + b] + g_rsumP[2 * BB + b] + g_rsumP[3 * BB + b];
        float inv = 1.0f / rs;
        v[0] = v[1] = v[2] = v[3] = 0.f;
#pragma unroll
        for (int kb = 0; kb < KSPLIT; kb++) {
            float4 p = *reinterpret_cast<const float4*>(
                g_part + ((size_t)kb * BB + b) * DD + t * 4);
            v[0] += p.x; v[1] += p.y; v[2] += p.z; v[3] += p.w;
        }
#pragma unroll
        for (int j = 0; j < 4; j++) v[j] *= inv;
    } else {
        float4 p = *reinterpret_cast<const float4*>(E + (size_t)node * DD + t * 4);
        v[0] = p.x; v[1] = p.y; v[2] = p.z; v[3] = p.w;
    }
    size_t o = (size_t)b * DD + t * 4;
    __half hi[4], lo[4];
#pragma unroll
    for (int j = 0; j < 4; j++) {
        hi[j] = __float2half_rn(v[j]);
        lo[j] = __float2half_rn(v[j] - __half2float(hi[j]));
    }
    *reinterpret_cast<__half2*>(g_hHi + o)     = __halves2half2(hi[0], hi[1]);
    *reinterpret_cast<__half2*>(g_hHi + o + 2) = __halves2half2(hi[2], hi[3]);
    *reinterpret_cast<__half2*>(g_hLo + o)     = __halves2half2(lo[0], lo[1]);
    *reinterpret_cast<__half2*>(g_hLo + o + 2) = __halves2half2(lo[2], lo[3]);
}

// ==================== 4) MLP layer: fp16 x-split (2 MMAs) + bias + relu ====================
__global__ void __launch_bounds__(512, 1) mlp_kernel(
    const __half* __restrict__ inHi, const __half* __restrict__ inLo,
    const __half* __restrict__ Wh,   const float* __restrict__ bias,
    __half* __restrict__ outHi, __half* __restrict__ outLo,
    float* __restrict__ outF) {
    const int i0 = blockIdx.x * 128;
    const int o0 = blockIdx.y * 64;
    extern __shared__ __align__(1024) char smem[];
    const uint32_t sb = smem_u32(smem);
    const int t = threadIdx.x, lane = t & 31, wid = t >> 5;
    const int wm = wid & 7, wn = wid >> 3;
    const uint32_t sINhi = sb;
    const uint32_t sINlo = sb + MLP_IN_PL;
    const uint32_t sW    = sb + 2 * MLP_IN_PL;

    auto load_half = [&](int h) {
#pragma unroll
        for (int i = 0; i < 4; i++) {
            int g = t + 512 * i;
            int m = g >> 4, s = (g & 15) + h * 16;
            uint32_t off = m * 512 + (uint32_t)((s * 16) ^ ((m & 7) << 4));
            CP16(sINhi + off, inHi + (size_t)(i0 + m) * DD + s * 8);
            CP16(sINlo + off, inLo + (size_t)(i0 + m) * DD + s * 8);
        }
#pragma unroll
        for (int i = 0; i < 2; i++) {
            int gg = t + 512 * i;
            int n = gg >> 4, s = (gg & 15) + h * 16;
            uint32_t off = n * 512 + (uint32_t)((s * 16) ^ ((n & 7) << 4));
            CP16(sW + off, Wh + (size_t)(o0 + n) * DD + s * 8);
        }
    };

    float acc[4][4];
#pragma unroll
    for (int f = 0; f < 4; f++)
#pragma unroll
        for (int q = 0; q < 4; q++) acc[f][q] = 0.f;

    auto comp_half = [&](int h) {
        const int q = lane >> 3, l7 = lane & 7;
#pragma unroll
        for (int ksl = 0; ksl < 8; ksl++) {
            const int ks = h * 8 + ksl;
            uint32_t ah[4], al[4];
            {
                const int m  = wm * 16 + (q & 1) * 8 + l7;
                const int kB = ks * 32 + (q >> 1) * 16;
                const uint32_t off = m * 512 + (uint32_t)(kB ^ ((m & 7) << 4));
                LDSM_X4(ah[0], ah[1], ah[2], ah[3], sINhi + off);
                LDSM_X4(al[0], al[1], al[2], al[3], sINlo + off);
            }
            uint32_t bh[2][4];
#pragma unroll
            for (int nn = 0; nn < 2; nn++) {
                const int n  = wn * 32 + nn * 16 + (q >> 1) * 8 + l7;
                const int kB = ks * 32 + (q & 1) * 16;
                const uint32_t off = n * 512 + (uint32_t)(kB ^ ((n & 7) << 4));
                LDSM_X4(bh[nn][0], bh[nn][1], bh[nn][2], bh[nn][3], sW + off);
            }
#pragma unroll
            for (int nn = 0; nn < 2; nn++) {
                float* d0 = acc[nn * 2];
                float* d1 = acc[nn * 2 + 1];
                MMA_F16(d0, ah[0], ah[1], ah[2], ah[3], bh[nn][0], bh[nn][1]);
                MMA_F16(d0, al[0], al[1], al[2], al[3], bh[nn][0], bh[nn][1]);
                MMA_F16(d1, ah[0], ah[1], ah[2], ah[3], bh[nn][2], bh[nn][3]);
                MMA_F16(d1, al[0], al[1], al[2], al[3], bh[nn][2], bh[nn][3]);
            }
        }
    };

    load_half(0); CP_COMMIT();
    load_half(1); CP_COMMIT();
    asm volatile("cp.async.wait_group 1;" ::: "memory");
    __syncthreads();
    comp_half(0);
    asm volatile("cp.async.wait_group 0;" ::: "memory");
    __syncthreads();
    comp_half(1);

    const int row0 = i0 + wm * 16 + (lane >> 2);
#pragma unroll
    for (int f = 0; f < 4; f++) {
        const int col = o0 + wn * 32 + f * 8 + (lane & 3) * 2;
        const float b0 = bias[col], b1 = bias[col + 1];
        float y00 = fmaxf(acc[f][0] + b0, 0.f);
        float y01 = fmaxf(acc[f][1] + b1, 0.f);
        float y10 = fmaxf(acc[f][2] + b0, 0.f);
        float y11 = fmaxf(acc[f][3] + b1, 0.f);
        if (outF) {
            *reinterpret_cast<float2*>(outF + (size_t)row0 * DD + col) = make_float2(y00, y01);
            *reinterpret_cast<float2*>(outF + (size_t)(row0 + 8) * DD + col) = make_float2(y10, y11);
        } else {
            float y[4] = {y00, y01, y10, y11};
            __half hi[4], lo[4];
#pragma unroll
            for (int j = 0; j < 4; j++) {
                hi[j] = __float2half_rn(y[j]);
                lo[j] = __float2half_rn(y[j] - __half2float(hi[j]));
            }
            *reinterpret_cast<__half2*>(outHi + (size_t)row0 * DD + col) = __halves2half2(hi[0], hi[1]);
            *reinterpret_cast<__half2*>(outHi + (size_t)(row0 + 8) * DD + col) = __halves2half2(hi[2], hi[3]);
            *reinterpret_cast<__half2*>(outLo + (size_t)row0 * DD + col) = __halves2half2(lo[0], lo[1]);
            *reinterpret_cast<__half2*>(outLo + (size_t)(row0 + 8) * DD + col) = __halves2half2(lo[2], lo[3]);
        }
    }
}

// ==================== launch ====================
extern "C" void kernel_launch(void* const* d_in, const int* in_sizes, int n_in,
                              void* d_out, int out_size) {
    const int*   labels = (const int*)d_in[0];
    const int*   nidx   = (const int*)d_in[1];
    const float* A      = (const float*)d_in[2];
    const float* E      = (const float*)d_in[3];
    const float* W      = (const float*)d_in[4];
    const float* bias   = (const float*)d_in[5];

    float* out        = (float*)d_out;
    float* out_labels = nullptr;
    float* out_h      = out;
    if (out_size >= BB * DD + BB) {
        out_labels = out;
        out_h      = out + BB;
    }

    __half *hHi, *hLo, *h2Hi, *h2Lo, *Wh;
    cudaGetSymbolAddress((void**)&hHi,  g_hHi);
    cudaGetSymbolAddress((void**)&hLo,  g_hLo);
    cudaGetSymbolAddress((void**)&h2Hi, g_h2Hi);
    cudaGetSymbolAddress((void**)&h2Lo, g_h2Lo);
    cudaGetSymbolAddress((void**)&Wh,   g_Wh);

    cudaFuncSetAttribute(gemm1_kernel,
                         cudaFuncAttributeMaxDynamicSharedMemorySize, GEMM_SMEM);
    cudaFuncSetAttribute(mlp_kernel,
                         cudaFuncAttributeMaxDynamicSharedMemorySize, MLP_SMEM);

    prep_kernel<<<PREP_GRID, 256>>>(labels, nidx, E, W, out_labels);
    gemm1_kernel<<<dim3(KSPLIT, BB / MT), 512, GEMM_SMEM>>>(A);
    finalize_kernel<<<BB, 64>>>(E);
    mlp_kernel<<<dim3(BB / 128, DD / 64), 512, MLP_SMEM>>>(
        hHi, hLo, Wh, bias, h2Hi, h2Lo, nullptr);
    mlp_kernel<<<dim3(BB / 128, DD / 64), 512, MLP_SMEM>>>(
        h2Hi, h2Lo, Wh + DD * DD, bias + DD, hHi, hLo, nullptr);
    mlp_kernel<<<dim3(BB / 128, DD / 64), 512, MLP_SMEM>>>(
        hHi, hLo, Wh + 2 * DD * DD, bias + 2 * DD, nullptr, nullptr, out_h);
}